// round 3
// baseline (speedup 1.0000x reference)
#include <cuda_runtime.h>
#include <cuda_fp16.h>
#include <cstdint>

// Problem dims (fixed)
#define N_IMG   8
#define C_IN    2048
#define HW      4096
#define C_OUT   512
#define M_TOTAL (N_IMG * HW)      // 32768

// GEMM tiling: BM=128 (p), BN=128 (out ch), BK=32 (in ch)
#define BM 128
#define BN 128
#define BK 32
#define KT (C_IN / BK)            // 64 k-iterations

// Smem tile strides (halfs), padded for conflict-free ldmatrix
#define AS_STRIDE 136             // 128 + 8 halfs  (row = one k, cols = m)
#define BS_STRIDE 40              // 32 + 8 halfs   (row = one n, cols = k)
#define A_TILE_H (BK * AS_STRIDE) // 4352 halfs
#define B_TILE_H (BN * BS_STRIDE) // 5120 halfs

// Weight center taps as fp16, [o][c]
__device__ __half g_B[C_OUT * C_IN];

__global__ void extract_w_kernel(const float* __restrict__ W) {
    int idx = blockIdx.x * 256 + threadIdx.x;     // over C_OUT*C_IN
    g_B[idx] = __float2half(W[(size_t)idx * 9 + 4]);
}

__device__ __forceinline__ uint32_t smem_u32(const void* p) {
    uint32_t a;
    asm("{ .reg .u64 t; cvta.to.shared.u64 t, %1; cvt.u32.u64 %0, t; }" : "=r"(a) : "l"(p));
    return a;
}

__device__ __forceinline__ void ldsm_x4(uint32_t& r0, uint32_t& r1, uint32_t& r2, uint32_t& r3,
                                        uint32_t addr) {
    asm volatile("ldmatrix.sync.aligned.m8n8.x4.shared.b16 {%0,%1,%2,%3}, [%4];"
                 : "=r"(r0), "=r"(r1), "=r"(r2), "=r"(r3) : "r"(addr));
}
__device__ __forceinline__ void ldsm_x4_t(uint32_t& r0, uint32_t& r1, uint32_t& r2, uint32_t& r3,
                                          uint32_t addr) {
    asm volatile("ldmatrix.sync.aligned.m8n8.x4.trans.shared.b16 {%0,%1,%2,%3}, [%4];"
                 : "=r"(r0), "=r"(r1), "=r"(r2), "=r"(r3) : "r"(addr));
}
__device__ __forceinline__ void mma16816(float* c, const uint32_t* a, const uint32_t* b) {
    asm volatile(
        "mma.sync.aligned.m16n8k16.row.col.f32.f16.f16.f32 "
        "{%0,%1,%2,%3}, {%4,%5,%6,%7}, {%8,%9}, {%0,%1,%2,%3};"
        : "+f"(c[0]), "+f"(c[1]), "+f"(c[2]), "+f"(c[3])
        : "r"(a[0]), "r"(a[1]), "r"(a[2]), "r"(a[3]), "r"(b[0]), "r"(b[1]));
}

// 256 threads = 8 warps; warp grid 4 (m) x 2 (n); warp tile 32 x 64
__global__ void __launch_bounds__(256, 1)
gemm_kernel(const float* __restrict__ fea, const float* __restrict__ bias,
            float* __restrict__ out) {
    __shared__ alignas(16) __half As[2][A_TILE_H];
    __shared__ alignas(16) __half Bs[2][B_TILE_H];

    const int tid   = threadIdx.x;
    const int lane  = tid & 31;
    const int wid   = tid >> 5;
    const int wm    = wid & 3;          // m-warp 0..3 -> m offset wm*32
    const int wn    = wid >> 2;         // n-warp 0..1 -> n offset wn*64
    const int ntile = blockIdx.x;       // 0..3
    const int mtile = blockIdx.y;       // 0..255

    const int m0   = mtile * BM;
    const int nimg = m0 >> 12;          // BM=128 tile never straddles images
    const int p0   = m0 & (HW - 1);

    // ---- global load addressing (per-thread, invariant except k offset) ----
    // A: 32 rows (c) x 128 floats (p). Thread t: row t>>3, 16 floats at (t&7)*16.
    const int ar  = tid >> 3;
    const int ac  = (tid & 7) * 16;
    const float* aPtr = fea + ((size_t)(nimg * C_IN + ar) * HW) + p0 + ac;
    // B: 128 rows (o) x 32 halfs (c). Thread t: row t>>1, 16 halfs at (t&1)*16.
    const int br  = tid >> 1;
    const int bc  = (tid & 1) * 16;
    const __half* bPtr = g_B + (size_t)(ntile * BN + br) * C_IN + bc;

    // smem store addrs (halfs)
    __half* aSts0 = &As[0][ar * AS_STRIDE + ac];
    __half* bSts0 = &Bs[0][br * BS_STRIDE + bc];

    // ---- ldmatrix lane addressing ----
    const int grp = lane >> 3, lr8 = lane & 7;
    // A (trans) from As[k][m]: k_add = (grp>>1)*8 + lr8 ; m_add = (grp&1)*8
    const uint32_t asU = smem_u32(&As[0][0]);
    const uint32_t bsU = smem_u32(&Bs[0][0]);
    const uint32_t aLane = (uint32_t)((((grp >> 1) * 8 + lr8) * AS_STRIDE
                                      + wm * 32 + (grp & 1) * 8) * 2);
    // B (no trans) from Bs[n][k]: n_add = (grp>>1)*8 + lr8 ; k_add = (grp&1)*8
    const uint32_t bLane = (uint32_t)(((wn * 64 + (grp >> 1) * 8 + lr8) * BS_STRIDE
                                      + (grp & 1) * 8) * 2);

    float acc[2][8][4];
#pragma unroll
    for (int i = 0; i < 2; i++)
#pragma unroll
        for (int j = 0; j < 8; j++)
#pragma unroll
            for (int q = 0; q < 4; q++) acc[i][j][q] = 0.f;

    float  ar_f[16];
    uint4  br_v[2];

    // ---- prologue: load tile 0, store to buffer 0 ----
#pragma unroll
    for (int i = 0; i < 4; i++)
        *reinterpret_cast<float4*>(&ar_f[i * 4]) =
            *reinterpret_cast<const float4*>(aPtr + i * 4);
    br_v[0] = *reinterpret_cast<const uint4*>(bPtr);
    br_v[1] = *reinterpret_cast<const uint4*>(bPtr + 8);
    {
        __half2 h[8];
#pragma unroll
        for (int i = 0; i < 8; i++) h[i] = __floats2half2_rn(ar_f[2 * i], ar_f[2 * i + 1]);
        reinterpret_cast<uint4*>(aSts0)[0] = *reinterpret_cast<uint4*>(&h[0]);
        reinterpret_cast<uint4*>(aSts0)[1] = *reinterpret_cast<uint4*>(&h[4]);
        reinterpret_cast<uint4*>(bSts0)[0] = br_v[0];
        reinterpret_cast<uint4*>(bSts0)[1] = br_v[1];
    }

    int cur = 0;
    for (int kt = 0; kt < KT; kt++) {
        __syncthreads();
        const bool more = (kt + 1 < KT);
        if (more) {
            const float* ap = aPtr + (size_t)(kt + 1) * BK * HW;
#pragma unroll
            for (int i = 0; i < 4; i++)
                *reinterpret_cast<float4*>(&ar_f[i * 4]) =
                    *reinterpret_cast<const float4*>(ap + i * 4);
            const __half* bp = bPtr + (kt + 1) * BK;
            br_v[0] = *reinterpret_cast<const uint4*>(bp);
            br_v[1] = *reinterpret_cast<const uint4*>(bp + 8);
        }

        // ---- compute on buffer cur ----
        const uint32_t aB = asU + (uint32_t)cur * (A_TILE_H * 2) + aLane;
        const uint32_t bB = bsU + (uint32_t)cur * (B_TILE_H * 2) + bLane;
#pragma unroll
        for (int ks = 0; ks < 2; ks++) {
            uint32_t aF[2][4], bF[8][2];
            const uint32_t aK = aB + (uint32_t)(ks * 16 * AS_STRIDE * 2);
            ldsm_x4_t(aF[0][0], aF[0][1], aF[0][2], aF[0][3], aK);
            ldsm_x4_t(aF[1][0], aF[1][1], aF[1][2], aF[1][3], aK + 32);  // +16 halfs (m)
            const uint32_t bK = bB + (uint32_t)(ks * 32);                // +16 halfs (k)
#pragma unroll
            for (int nbp = 0; nbp < 4; nbp++) {
                ldsm_x4(bF[2 * nbp][0], bF[2 * nbp][1], bF[2 * nbp + 1][0], bF[2 * nbp + 1][1],
                        bK + (uint32_t)(nbp * 16 * BS_STRIDE * 2));
            }
#pragma unroll
            for (int mb = 0; mb < 2; mb++)
#pragma unroll
                for (int nb = 0; nb < 8; nb++)
                    mma16816(acc[mb][nb], aF[mb], bF[nb]);
        }

        if (more) {
            const int nxt = cur ^ 1;
            __half2 h[8];
#pragma unroll
            for (int i = 0; i < 8; i++) h[i] = __floats2half2_rn(ar_f[2 * i], ar_f[2 * i + 1]);
            __half* asd = aSts0 + nxt * A_TILE_H;
            __half* bsd = bSts0 + nxt * B_TILE_H;
            reinterpret_cast<uint4*>(asd)[0] = *reinterpret_cast<uint4*>(&h[0]);
            reinterpret_cast<uint4*>(asd)[1] = *reinterpret_cast<uint4*>(&h[4]);
            reinterpret_cast<uint4*>(bsd)[0] = br_v[0];
            reinterpret_cast<uint4*>(bsd)[1] = br_v[1];
            cur = nxt;
        }
    }

    // ---- epilogue: bias + relu, direct STG ----
    const int lr = lane >> 2;          // 0..7 (p within 16-row block)
    const int lc = (lane & 3) * 2;     // 0,2,4,6 (o within 8-col block)
    const int oBase = ntile * BN + wn * 64 + lc;
    const int pBase = p0 + wm * 32 + lr;
    float* outN = out + ((size_t)nimg * C_OUT) * HW;

#pragma unroll
    for (int nb = 0; nb < 8; nb++) {
        const int o = oBase + nb * 8;
        const float b0 = bias[o], b1 = bias[o + 1];
        float* r0p = outN + (size_t)o * HW;
        float* r1p = outN + (size_t)(o + 1) * HW;
#pragma unroll
        for (int mb = 0; mb < 2; mb++) {
            const int p  = pBase + mb * 16;
            float v0 = acc[mb][nb][0] + b0;
            float v1 = acc[mb][nb][1] + b1;
            float v2 = acc[mb][nb][2] + b0;
            float v3 = acc[mb][nb][3] + b1;
            r0p[p]     = v0 > 0.f ? v0 : 0.f;
            r1p[p]     = v1 > 0.f ? v1 : 0.f;
            r0p[p + 8] = v2 > 0.f ? v2 : 0.f;
            r1p[p + 8] = v3 > 0.f ? v3 : 0.f;
        }
    }
}

extern "C" void kernel_launch(void* const* d_in, const int* in_sizes, int n_in,
                              void* d_out, int out_size) {
    const float* fea = (const float*)d_in[0];
    const float* W   = (const float*)d_in[1];
    const float* b   = (const float*)d_in[2];
    float* out       = (float*)d_out;

    extract_w_kernel<<<(C_OUT * C_IN) / 256, 256>>>(W);
    // ntile fastest (blockIdx.x) so CTAs sharing an A m-tile run together -> L2 reuse
    gemm_kernel<<<dim3(C_OUT / BN, M_TOTAL / BM), 256>>>(fea, b, out);
}

// round 4
// speedup vs baseline: 1.9039x; 1.9039x over previous
#include <cuda_runtime.h>
#include <cuda_fp16.h>
#include <cstdint>

// Problem dims (fixed)
#define N_IMG   8
#define C_IN    2048
#define HW      4096
#define C_OUT   512
#define M_TOTAL (N_IMG * HW)      // 32768

// GEMM tiling
#define BM 128
#define BN 128
#define BK 64
#define KT (C_IN / BK)            // 32
#define STAGES 3
#define A_STAGE_BYTES 16384       // 64 k-rows x 256B (128 halfs of m)
#define B_STAGE_BYTES 16384       // 128 n-rows x 128B (64 halfs of k)
#define STAGE_BYTES   32768
#define SMEM_DYN (STAGES * STAGE_BYTES)   // 98304

// fp16 scratch (device globals; no allocs)
__device__ __half g_A[(size_t)M_TOTAL * C_IN];   // [n][c][p] layout preserved, fp16
__device__ __half g_B[C_OUT * C_IN];             // [o][c] center taps

// ---------------- pre-pass kernels ----------------
__global__ void extract_w_kernel(const float* __restrict__ W) {
    int idx = blockIdx.x * 256 + threadIdx.x;     // over C_OUT*C_IN
    g_B[idx] = __float2half(W[(size_t)idx * 9 + 4]);
}

__global__ void convert_a_kernel(const float4* __restrict__ fea) {
    size_t i = (size_t)blockIdx.x * 256 + threadIdx.x;   // 16Mi float4's
    float4 v = fea[i];
    __half2 h0 = __floats2half2_rn(v.x, v.y);
    __half2 h1 = __floats2half2_rn(v.z, v.w);
    uint2 o;
    o.x = *reinterpret_cast<uint32_t*>(&h0);
    o.y = *reinterpret_cast<uint32_t*>(&h1);
    reinterpret_cast<uint2*>(g_A)[i] = o;
}

// ---------------- helpers ----------------
__device__ __forceinline__ uint32_t smem_u32(const void* p) {
    uint32_t a;
    asm("{ .reg .u64 t; cvta.to.shared.u64 t, %1; cvt.u32.u64 %0, t; }" : "=r"(a) : "l"(p));
    return a;
}
__device__ __forceinline__ void cp16(uint32_t s, const void* g) {
    asm volatile("cp.async.cg.shared.global [%0], [%1], 16;" :: "r"(s), "l"(g));
}
#define CP_COMMIT() asm volatile("cp.async.commit_group;" ::: "memory")
#define CP_WAIT1()  asm volatile("cp.async.wait_group 1;" ::: "memory")
#define CP_WAIT0()  asm volatile("cp.async.wait_group 0;" ::: "memory")

__device__ __forceinline__ void ldsm_x4(uint32_t& r0, uint32_t& r1, uint32_t& r2, uint32_t& r3,
                                        uint32_t addr) {
    asm volatile("ldmatrix.sync.aligned.m8n8.x4.shared.b16 {%0,%1,%2,%3}, [%4];"
                 : "=r"(r0), "=r"(r1), "=r"(r2), "=r"(r3) : "r"(addr));
}
__device__ __forceinline__ void ldsm_x4_t(uint32_t& r0, uint32_t& r1, uint32_t& r2, uint32_t& r3,
                                          uint32_t addr) {
    asm volatile("ldmatrix.sync.aligned.m8n8.x4.trans.shared.b16 {%0,%1,%2,%3}, [%4];"
                 : "=r"(r0), "=r"(r1), "=r"(r2), "=r"(r3) : "r"(addr));
}
__device__ __forceinline__ void mma16816(float* c, const uint32_t* a, const uint32_t* b) {
    asm volatile(
        "mma.sync.aligned.m16n8k16.row.col.f32.f16.f16.f32 "
        "{%0,%1,%2,%3}, {%4,%5,%6,%7}, {%8,%9}, {%0,%1,%2,%3};"
        : "+f"(c[0]), "+f"(c[1]), "+f"(c[2]), "+f"(c[3])
        : "r"(a[0]), "r"(a[1]), "r"(a[2]), "r"(a[3]), "r"(b[0]), "r"(b[1]));
}

// ---------------- GEMM: 128 threads = 4 warps, warp tile 64x64 ----------------
__global__ void __launch_bounds__(128, 2)
gemm_kernel(const float* __restrict__ bias, float* __restrict__ out) {
    extern __shared__ char smem[];
    const uint32_t sb = smem_u32(smem);

    const int tid  = threadIdx.x;
    const int lane = tid & 31;
    const int wid  = tid >> 5;
    const int wm   = wid & 1;           // m-warp: offset wm*64
    const int wn   = wid >> 1;          // n-warp: offset wn*64
    const int ntile = blockIdx.x;       // 0..3
    const int mtile = blockIdx.y;       // 0..255

    const int m0   = mtile * BM;
    const int nimg = m0 >> 12;
    const int p0   = m0 & (HW - 1);

    // ---- cp.async addressing (8 A-chunks + 8 B-chunks per thread) ----
    const __half* aB0 = g_A + (size_t)nimg * C_IN * HW + p0;
    const __half* bB0 = g_B + (size_t)ntile * BN * C_IN;

    uint32_t aSw[8], bSw[8];
    const __half* aSrc[8];
    const __half* bSrc[8];
#pragma unroll
    for (int j = 0; j < 8; j++) {
        int ca   = tid + 128 * j;          // 0..1023
        int arow = ca >> 4;                // k-row 0..63
        int ac16 = ca & 15;                // 16B chunk in 256B row
        aSw[j]  = (uint32_t)(arow * 256 + ((ac16 ^ (arow & 7)) << 4));
        aSrc[j] = aB0 + (size_t)arow * HW + ac16 * 8;

        int cb   = tid + 128 * j;
        int brow = cb >> 3;                // n-row 0..127
        int bc16 = cb & 7;
        bSw[j]  = (uint32_t)(A_STAGE_BYTES + brow * 128 + ((bc16 ^ (brow & 7)) << 4));
        bSrc[j] = bB0 + (size_t)brow * C_IN + bc16 * 8;
    }

    // ---- ldmatrix lane addressing ----
    const int grp = lane >> 3, lr8 = lane & 7;
    const int krl    = (grp >> 1) * 8 + lr8;          // k row local 0..15
    const int ac16b  = wm * 8 + (grp & 1);            // A m-chunk base (c16)
    const int nrl    = (grp >> 1) * 8 + lr8;          // n row local 0..15
    // A frag smem offsets per mb (xor indep of ks since 16 | 8-period)
    uint32_t aOff[4];
#pragma unroll
    for (int mb = 0; mb < 4; mb++)
        aOff[mb] = (uint32_t)(krl * 256 + (((ac16b + 2 * mb) ^ (krl & 7)) << 4));

    float acc[4][8][4];
#pragma unroll
    for (int i = 0; i < 4; i++)
#pragma unroll
        for (int j = 0; j < 8; j++)
#pragma unroll
            for (int q = 0; q < 4; q++) acc[i][j][q] = 0.f;

    // ---- prologue: stages 0,1 ----
#pragma unroll
    for (int s = 0; s < 2; s++) {
        const uint32_t st = sb + s * STAGE_BYTES;
#pragma unroll
        for (int j = 0; j < 8; j++) cp16(st + aSw[j], aSrc[j] + (size_t)s * BK * HW);
#pragma unroll
        for (int j = 0; j < 8; j++) cp16(st + bSw[j], bSrc[j] + s * BK);
        CP_COMMIT();
    }

    for (int kt = 0; kt < KT; kt++) {
        if (kt < KT - 1) { CP_WAIT1(); } else { CP_WAIT0(); }
        __syncthreads();

        // issue stage kt+2 (overwrites stage computed at kt-1; safe after sync)
        if (kt + 2 < KT) {
            const int s = (kt + 2) % STAGES;
            const uint32_t st = sb + s * STAGE_BYTES;
#pragma unroll
            for (int j = 0; j < 8; j++) cp16(st + aSw[j], aSrc[j] + (size_t)(kt + 2) * BK * HW);
#pragma unroll
            for (int j = 0; j < 8; j++) cp16(st + bSw[j], bSrc[j] + (kt + 2) * BK);
            CP_COMMIT();
        }

        // ---- compute stage kt%3 ----
        const uint32_t aBase = sb + (kt % STAGES) * STAGE_BYTES;
        const uint32_t bBase = aBase;   // bSw already carries +A_STAGE_BYTES
#pragma unroll
        for (int ks = 0; ks < 4; ks++) {
            uint32_t aF[4][4], bF[8][2];
#pragma unroll
            for (int mb = 0; mb < 4; mb++)
                ldsm_x4_t(aF[mb][0], aF[mb][1], aF[mb][2], aF[mb][3],
                          aBase + aOff[mb] + (uint32_t)(ks * 4096));
#pragma unroll
            for (int nbp = 0; nbp < 4; nbp++) {
                const int nrow = wn * 64 + nbp * 16 + nrl;
                const uint32_t ba = bBase + (uint32_t)(A_STAGE_BYTES + nrow * 128
                                   + (((ks * 2 + (grp & 1)) ^ (nrow & 7)) << 4));
                ldsm_x4(bF[2 * nbp][0], bF[2 * nbp][1], bF[2 * nbp + 1][0], bF[2 * nbp + 1][1], ba);
            }
#pragma unroll
            for (int mb = 0; mb < 4; mb++)
#pragma unroll
                for (int nb = 0; nb < 8; nb++)
                    mma16816(acc[mb][nb], aF[mb], bF[nb]);
        }
    }

    // ---- epilogue: bias + relu, direct STG ----
    const int lr = lane >> 2;           // p within 16-block
    const int lc = (lane & 3) * 2;      // o within 8-block
    const int oBase = ntile * BN + wn * 64 + lc;
    const int pBase = p0 + wm * 64 + lr;
    float* outN = out + (size_t)nimg * C_OUT * HW;

#pragma unroll
    for (int nb = 0; nb < 8; nb++) {
        const int o = oBase + nb * 8;
        const float b0 = bias[o], b1 = bias[o + 1];
        float* r0p = outN + (size_t)o * HW;
        float* r1p = outN + (size_t)(o + 1) * HW;
#pragma unroll
        for (int mb = 0; mb < 4; mb++) {
            const int p = pBase + mb * 16;
            float v0 = acc[mb][nb][0] + b0;
            float v1 = acc[mb][nb][1] + b1;
            float v2 = acc[mb][nb][2] + b0;
            float v3 = acc[mb][nb][3] + b1;
            r0p[p]     = v0 > 0.f ? v0 : 0.f;
            r1p[p]     = v1 > 0.f ? v1 : 0.f;
            r0p[p + 8] = v2 > 0.f ? v2 : 0.f;
            r1p[p + 8] = v3 > 0.f ? v3 : 0.f;
        }
    }
}

// ---------------- launch ----------------
extern "C" void kernel_launch(void* const* d_in, const int* in_sizes, int n_in,
                              void* d_out, int out_size) {
    const float* fea = (const float*)d_in[0];
    const float* W   = (const float*)d_in[1];
    const float* b   = (const float*)d_in[2];
    float* out       = (float*)d_out;

    cudaFuncSetAttribute(gemm_kernel, cudaFuncAttributeMaxDynamicSharedMemorySize, SMEM_DYN);

    extract_w_kernel<<<(C_OUT * C_IN) / 256, 256>>>(W);
    convert_a_kernel<<<(M_TOTAL / 4) * (C_IN / 256), 256>>>((const float4*)fea);
    // ntile fastest so CTAs sharing an A m-tile co-run -> L2 dedup of A
    gemm_kernel<<<dim3(C_OUT / BN, M_TOTAL / BM), 128, SMEM_DYN>>>(b, out);
}

// round 6
// speedup vs baseline: 2.1703x; 1.1399x over previous
#include <cuda_runtime.h>
#include <cuda_fp16.h>
#include <cstdint>

// Problem dims (fixed)
#define N_IMG   8
#define C_IN    2048
#define HW      4096
#define C_OUT   512
#define M_TOTAL (N_IMG * HW)      // 32768

// GEMM tiling
#define BM 128
#define BN 128
#define BK 64
#define KT (C_IN / BK)            // 32
#define STAGES 3
#define A_STAGE_BYTES 16384       // 64 k-rows x 256B (128 halfs of m)
#define STAGE_BYTES   32768       // + 16KB B (128 n-rows x 128B)
#define SMEM_DYN (STAGES * STAGE_BYTES)   // 98304

// Weight center taps as fp16, [o][c]
__device__ __half g_B[C_OUT * C_IN];

// ---------------- pre-pass ----------------
__global__ void extract_w_kernel(const float* __restrict__ W) {
    int i4 = (blockIdx.x * 256 + threadIdx.x) * 4;   // over C_OUT*C_IN, 4/thread
    __half h[4];
#pragma unroll
    for (int i = 0; i < 4; i++)
        h[i] = __float2half(W[(size_t)(i4 + i) * 9 + 4]);
    *reinterpret_cast<uint2*>(&g_B[i4]) = *reinterpret_cast<uint2*>(h);
}

// ---------------- helpers ----------------
__device__ __forceinline__ uint32_t smem_u32(const void* p) {
    uint32_t a;
    asm("{ .reg .u64 t; cvta.to.shared.u64 t, %1; cvt.u32.u64 %0, t; }" : "=r"(a) : "l"(p));
    return a;
}
__device__ __forceinline__ void cp16(uint32_t s, const void* g) {
    asm volatile("cp.async.cg.shared.global [%0], [%1], 16;" :: "r"(s), "l"(g));
}
#define CP_COMMIT() asm volatile("cp.async.commit_group;" ::: "memory")
#define CP_WAIT1()  asm volatile("cp.async.wait_group 1;" ::: "memory")
#define CP_WAIT0()  asm volatile("cp.async.wait_group 0;" ::: "memory")

__device__ __forceinline__ void sts128(uint32_t addr, uint32_t r0, uint32_t r1,
                                       uint32_t r2, uint32_t r3) {
    asm volatile("st.shared.v4.b32 [%0], {%1,%2,%3,%4};"
                 :: "r"(addr), "r"(r0), "r"(r1), "r"(r2), "r"(r3) : "memory");
}
__device__ __forceinline__ void ldsm_x4(uint32_t& r0, uint32_t& r1, uint32_t& r2, uint32_t& r3,
                                        uint32_t addr) {
    asm volatile("ldmatrix.sync.aligned.m8n8.x4.shared.b16 {%0,%1,%2,%3}, [%4];"
                 : "=r"(r0), "=r"(r1), "=r"(r2), "=r"(r3) : "r"(addr));
}
__device__ __forceinline__ void ldsm_x4_t(uint32_t& r0, uint32_t& r1, uint32_t& r2, uint32_t& r3,
                                          uint32_t addr) {
    asm volatile("ldmatrix.sync.aligned.m8n8.x4.trans.shared.b16 {%0,%1,%2,%3}, [%4];"
                 : "=r"(r0), "=r"(r1), "=r"(r2), "=r"(r3) : "r"(addr));
}
__device__ __forceinline__ void mma16816(float* c, const uint32_t* a, const uint32_t* b) {
    asm volatile(
        "mma.sync.aligned.m16n8k16.row.col.f32.f16.f16.f32 "
        "{%0,%1,%2,%3}, {%4,%5,%6,%7}, {%8,%9}, {%0,%1,%2,%3};"
        : "+f"(c[0]), "+f"(c[1]), "+f"(c[2]), "+f"(c[3])
        : "r"(a[0]), "r"(a[1]), "r"(a[2]), "r"(a[3]), "r"(b[0]), "r"(b[1]));
}
__device__ __forceinline__ void cvt_sts(uint32_t addr, const float4& v0, const float4& v1) {
    __half2 h0 = __floats2half2_rn(v0.x, v0.y);
    __half2 h1 = __floats2half2_rn(v0.z, v0.w);
    __half2 h2 = __floats2half2_rn(v1.x, v1.y);
    __half2 h3 = __floats2half2_rn(v1.z, v1.w);
    sts128(addr, *reinterpret_cast<uint32_t*>(&h0), *reinterpret_cast<uint32_t*>(&h1),
                 *reinterpret_cast<uint32_t*>(&h2), *reinterpret_cast<uint32_t*>(&h3));
}

// ---------------- GEMM: 128 threads = 4 warps, warp tile 64x64 ----------------
// A (fp32) loaded from fea directly, converted to fp16 in-register, STS'd.
__global__ void __launch_bounds__(128, 2)
gemm_kernel(const float* __restrict__ fea, const float* __restrict__ bias,
            float* __restrict__ out) {
    extern __shared__ char smem[];
    const uint32_t sb = smem_u32(smem);

    const int tid  = threadIdx.x;
    const int lane = tid & 31;
    const int wid  = tid >> 5;
    const int wm   = wid & 1;           // m-warp: offset wm*64
    const int wn   = wid >> 1;          // n-warp: offset wn*64
    const int ntile = blockIdx.x;       // 0..3
    const int mtile = blockIdx.y;       // 0..255

    const int m0   = mtile * BM;
    const int nimg = m0 >> 12;
    const int p0   = m0 & (HW - 1);

    // ---- A global-load addressing: per-thread base + immediate j-offsets ----
    // fp16 chunk id c = tid + 128*j ; arow = (tid>>4) + 8*j ; hc = tid&15
    const int arow0 = tid >> 4;
    const int ahc   = tid & 15;
    const float* aSrc = fea + (size_t)nimg * C_IN * HW + (size_t)arow0 * HW + p0 + ahc * 8;
    const uint32_t aSts0 = (uint32_t)(arow0 * 256 + ((ahc ^ (arow0 & 7)) << 4)); // +j*2048

    // ---- B cp.async addressing ----
    const int brow0 = tid >> 3;
    const int bhc   = tid & 7;
    const __half* bSrc = g_B + (size_t)(ntile * BN + brow0) * C_IN + bhc * 8;
    const uint32_t bSts0 = (uint32_t)(A_STAGE_BYTES + brow0 * 128
                                      + ((bhc ^ (brow0 & 7)) << 4));             // +j*2048

    // ---- ldmatrix lane addressing ----
    const int grp = lane >> 3, lr8 = lane & 7;
    const int krl   = (grp >> 1) * 8 + lr8;
    const int ac16b = wm * 8 + (grp & 1);
    const int nrl   = (grp >> 1) * 8 + lr8;
    uint32_t aOff[4];
#pragma unroll
    for (int mb = 0; mb < 4; mb++)
        aOff[mb] = (uint32_t)(krl * 256 + (((ac16b + 2 * mb) ^ (krl & 7)) << 4));

    float acc[4][8][4];
#pragma unroll
    for (int i = 0; i < 4; i++)
#pragma unroll
        for (int j = 0; j < 8; j++)
#pragma unroll
            for (int q = 0; q < 4; q++) acc[i][j][q] = 0.f;

    // ---- prologue: stages 0,1 ----
#pragma unroll
    for (int s = 0; s < 2; s++) {
        const uint32_t st = sb + s * STAGE_BYTES;
        const float* ap = aSrc + (size_t)s * BK * HW;
#pragma unroll
        for (int j = 0; j < 8; j++) {
            float4 v0 = *reinterpret_cast<const float4*>(ap + (size_t)j * 8 * HW);
            float4 v1 = *reinterpret_cast<const float4*>(ap + (size_t)j * 8 * HW + 4);
            cvt_sts(st + aSts0 + j * 2048, v0, v1);
        }
#pragma unroll
        for (int j = 0; j < 8; j++)
            cp16(st + bSts0 + j * 2048, bSrc + s * BK + j * 16 * C_IN);
        CP_COMMIT();
    }

    for (int kt = 0; kt < KT; kt++) {
        if (kt < KT - 1) { CP_WAIT1(); } else { CP_WAIT0(); }
        __syncthreads();

        // issue A loads (fp32) for tile kt+2 early; consume after compute
        float4 av0[8], av1[8];
        const bool pf = (kt + 2 < KT);
        if (pf) {
            const float* ap = aSrc + (size_t)(kt + 2) * BK * HW;
#pragma unroll
            for (int j = 0; j < 8; j++) {
                av0[j] = *reinterpret_cast<const float4*>(ap + (size_t)j * 8 * HW);
                av1[j] = *reinterpret_cast<const float4*>(ap + (size_t)j * 8 * HW + 4);
            }
        }

        // ---- compute stage kt%3 ----
        const uint32_t base = sb + (kt % STAGES) * STAGE_BYTES;
#pragma unroll
        for (int ks = 0; ks < 4; ks++) {
            uint32_t aF[4][4], bF[8][2];
#pragma unroll
            for (int mb = 0; mb < 4; mb++)
                ldsm_x4_t(aF[mb][0], aF[mb][1], aF[mb][2], aF[mb][3],
                          base + aOff[mb] + (uint32_t)(ks * 4096));
#pragma unroll
            for (int nbp = 0; nbp < 4; nbp++) {
                const int nrow = wn * 64 + nbp * 16 + nrl;
                const uint32_t ba = base + (uint32_t)(A_STAGE_BYTES + nrow * 128
                                   + (((ks * 2 + (grp & 1)) ^ (nrow & 7)) << 4));
                ldsm_x4(bF[2 * nbp][0], bF[2 * nbp][1], bF[2 * nbp + 1][0], bF[2 * nbp + 1][1], ba);
            }
#pragma unroll
            for (int mb = 0; mb < 4; mb++)
#pragma unroll
                for (int nb = 0; nb < 8; nb++)
                    mma16816(acc[mb][nb], aF[mb], bF[nb]);
        }

        // ---- store tile kt+2 (slot (kt+2)%3, freed by the sync above) ----
        if (pf) {
            const uint32_t st = sb + ((kt + 2) % STAGES) * STAGE_BYTES;
#pragma unroll
            for (int j = 0; j < 8; j++)
                cvt_sts(st + aSts0 + j * 2048, av0[j], av1[j]);
#pragma unroll
            for (int j = 0; j < 8; j++)
                cp16(st + bSts0 + j * 2048, bSrc + (kt + 2) * BK + j * 16 * C_IN);
            CP_COMMIT();
        }
    }

    // ---- epilogue: bias + relu, direct STG ----
    const int lr = lane >> 2;
    const int lc = (lane & 3) * 2;
    const int oBase = ntile * BN + wn * 64 + lc;
    const int pBase = p0 + wm * 64 + lr;
    float* outN = out + (size_t)nimg * C_OUT * HW;

#pragma unroll
    for (int nb = 0; nb < 8; nb++) {
        const int o = oBase + nb * 8;
        const float b0 = bias[o], b1 = bias[o + 1];
        float* r0p = outN + (size_t)o * HW;
        float* r1p = outN + (size_t)(o + 1) * HW;
#pragma unroll
        for (int mb = 0; mb < 4; mb++) {
            const int p = pBase + mb * 16;
            float v0 = acc[mb][nb][0] + b0;
            float v1 = acc[mb][nb][1] + b1;
            float v2 = acc[mb][nb][2] + b0;
            float v3 = acc[mb][nb][3] + b1;
            r0p[p]     = v0 > 0.f ? v0 : 0.f;
            r1p[p]     = v1 > 0.f ? v1 : 0.f;
            r0p[p + 8] = v2 > 0.f ? v2 : 0.f;
            r1p[p + 8] = v3 > 0.f ? v3 : 0.f;
        }
    }
}

// ---------------- launch ----------------
extern "C" void kernel_launch(void* const* d_in, const int* in_sizes, int n_in,
                              void* d_out, int out_size) {
    const float* fea = (const float*)d_in[0];
    const float* W   = (const float*)d_in[1];
    const float* b   = (const float*)d_in[2];
    float* out       = (float*)d_out;

    cudaFuncSetAttribute(gemm_kernel, cudaFuncAttributeMaxDynamicSharedMemorySize, SMEM_DYN);

    extract_w_kernel<<<(C_OUT * C_IN) / 1024, 256>>>(W);
    // ntile fastest so the 4 CTAs sharing an A m-tile co-run -> L2 dedup of fp32 A
    gemm_kernel<<<dim3(C_OUT / BN, M_TOTAL / BM), 128, SMEM_DYN>>>(fea, b, out);
}